// round 2
// baseline (speedup 1.0000x reference)
#include <cuda_runtime.h>
#include <math.h>

#define SQ   1024
#define HIDN 4096
#define NH   32
#define HD   128
#define KBN  2048
#define KBSTRIDE 8192   // NUM_SLOTS * HID
#define NTOP 100
#define ATT_SCALE 0.08838834764831845f  // 1/sqrt(128)

#define BMQ 64
#define BNK 64
#define ATTN_SMEM ((BMQ*HD + BNK*HD + BMQ*(BNK+1) + 3*BMQ) * 4)

// ---------------- device scratch (static, allocation-free) ----------------
__device__ float g_xq  [SQ*HIDN];
__device__ float g_xq2 [SQ*HIDN];
__device__ float g_xk  [SQ*HIDN];
__device__ float g_xv  [SQ*HIDN];
__device__ float g_attn[SQ*HIDN];
__device__ float g_q2sum[HIDN];
__device__ float g_kbscore[KBN];
__device__ int   g_topidx[NTOP];

// ---------------- GEMM: C[m,n] = sum_k A[m,k] * B[n,k]  (A:MxK, B:NxK) ----
__global__ __launch_bounds__(256) void gemm_nt(
    const float* __restrict__ A, const float* __restrict__ B,
    float* __restrict__ C, int M, int N, int K)
{
    __shared__ float As[8][132];
    __shared__ float Bs[8][132];
    int bm = blockIdx.y * 128, bn = blockIdx.x * 128;
    int tid = threadIdx.x;
    int tx = tid & 15, ty = tid >> 4;
    int lr = tid >> 1, lc = (tid & 1) * 4;
    float acc[8][8];
    #pragma unroll
    for (int i = 0; i < 8; i++)
        #pragma unroll
        for (int j = 0; j < 8; j++) acc[i][j] = 0.f;

    const float* Ap = A + (size_t)(bm + lr) * K + lc;
    const float* Bp = B + (size_t)(bn + lr) * K + lc;

    for (int k0 = 0; k0 < K; k0 += 8) {
        float4 av = *(const float4*)(Ap + k0);
        float4 bv = *(const float4*)(Bp + k0);
        As[lc+0][lr]=av.x; As[lc+1][lr]=av.y; As[lc+2][lr]=av.z; As[lc+3][lr]=av.w;
        Bs[lc+0][lr]=bv.x; Bs[lc+1][lr]=bv.y; Bs[lc+2][lr]=bv.z; Bs[lc+3][lr]=bv.w;
        __syncthreads();
        #pragma unroll
        for (int kk = 0; kk < 8; kk++) {
            float4 a0 = *(const float4*)&As[kk][ty*8];
            float4 a1 = *(const float4*)&As[kk][ty*8+4];
            float4 b0 = *(const float4*)&Bs[kk][tx*8];
            float4 b1 = *(const float4*)&Bs[kk][tx*8+4];
            float a[8] = {a0.x,a0.y,a0.z,a0.w,a1.x,a1.y,a1.z,a1.w};
            float b[8] = {b0.x,b0.y,b0.z,b0.w,b1.x,b1.y,b1.z,b1.w};
            #pragma unroll
            for (int i = 0; i < 8; i++)
                #pragma unroll
                for (int j = 0; j < 8; j++)
                    acc[i][j] += a[i]*b[j];
        }
        __syncthreads();
    }
    #pragma unroll
    for (int i = 0; i < 8; i++) {
        float* Cp = C + (size_t)(bm + ty*8 + i) * N + bn + tx*8;
        *(float4*)Cp     = make_float4(acc[i][0],acc[i][1],acc[i][2],acc[i][3]);
        *(float4*)(Cp+4) = make_float4(acc[i][4],acc[i][5],acc[i][6],acc[i][7]);
    }
}

// ---------------- RoPE in place on g_xq and g_xk --------------------------
__global__ void rope_kernel(const int* __restrict__ pos_ids)
{
    const int total = SQ * HIDN / 2;   // pairs per tensor
    int i = blockIdx.x * blockDim.x + threadIdx.x;
    float* X = g_xq;
    if (i >= total) { X = g_xk; i -= total; }
    if (i >= total) return;
    int s = i / (HIDN/2);
    int r = i - s * (HIDN/2);
    int h = r >> 6, d = r & 63;
    int c = s*HIDN + h*HD + d;
    float pos = (float)pos_ids[s];
    // inv = theta^(-2d/D) = exp(-d * ln(10000)/64)
    float inv = expf((float)d * (-9.210340371976184f / 64.0f));
    float f = pos * inv;
    float cs, sn;
    sincosf(f, &sn, &cs);
    float x1 = X[c], x2 = X[c + 64];
    X[c]      = x1*cs - x2*sn;
    X[c + 64] = x2*cs + x1*sn;
}

// ---------------- column sum of X2 (for kb score shortcut) ----------------
__global__ void colsum_kernel()
{
    int c = blockIdx.x * 256 + threadIdx.x;
    float s = 0.f;
    for (int r = 0; r < SQ; r++) s += g_xq2[(size_t)r*HIDN + c];
    g_q2sum[c] = s;
}

// ---------------- kb_scores[kb] = dot(kb_keys[kb,:HID], q2sum) ------------
__global__ void kbscore_kernel(const float* __restrict__ kb_keys)
{
    int kb   = blockIdx.x * 8 + (threadIdx.x >> 5);
    int lane = threadIdx.x & 31;
    const float* row = kb_keys + (size_t)kb * KBSTRIDE;
    float s = 0.f;
    for (int i = lane; i < HIDN; i += 32) s += row[i] * g_q2sum[i];
    #pragma unroll
    for (int o = 16; o; o >>= 1) s += __shfl_xor_sync(0xffffffffu, s, o);
    if (lane == 0) g_kbscore[kb] = s;   // positive monotonic scale omitted
}

// ---------------- top-100 by iterative argmax (single block) --------------
__global__ void topk_kernel()
{
    __shared__ float sv[KBN];
    __shared__ float rv[256];
    __shared__ int   ri[256];
    int t = threadIdx.x;
    for (int i = t; i < KBN; i += 256) sv[i] = g_kbscore[i];
    __syncthreads();
    for (int it = 0; it < NTOP; it++) {
        float best = -INFINITY; int bi = 0;
        for (int i = t; i < KBN; i += 256) {
            float v = sv[i];
            if (v > best) { best = v; bi = i; }
        }
        rv[t] = best; ri[t] = bi;
        __syncthreads();
        for (int o = 128; o; o >>= 1) {
            if (t < o && rv[t+o] > rv[t]) { rv[t] = rv[t+o]; ri[t] = ri[t+o]; }
            __syncthreads();
        }
        if (t == 0) { g_topidx[it] = ri[0]; sv[ri[0]] = -INFINITY; }
        __syncthreads();
    }
}

// ---------------- flash attention over [KB-topk ; causal self] ------------
__global__ __launch_bounds__(256) void attn_kernel(
    const float* __restrict__ kb_keys, const float* __restrict__ kb_values,
    const float* __restrict__ score_shift)
{
    extern __shared__ float sm[];
    float* Qs   = sm;                         // BMQ * 128
    float* KVs  = Qs  + BMQ*HD;               // BNK * 128
    float* Ss   = KVs + BNK*HD;               // BMQ * (BNK+1)
    float* mrow = Ss  + BMQ*(BNK+1);
    float* lrow = mrow + BMQ;
    float* crow = lrow + BMQ;

    int h  = blockIdx.y;
    int q0 = blockIdx.x * BMQ;
    int tid = threadIdx.x;
    int tx = tid & 15, ty = tid >> 4;   // score tile mapping (16x16)
    int qo = tid >> 2;                  // owned query row (0..63)
    int dc = (tid & 3) * 32;            // owned dim chunk base

    float acc[32];
    #pragma unroll
    for (int i = 0; i < 32; i++) acc[i] = 0.f;
    if (tid < BMQ) { mrow[tid] = -INFINITY; lrow[tid] = 0.f; }

    float shift = score_shift[h];

    const int nkb    = (NTOP + BNK - 1) / BNK;   // 2
    const int ntiles = nkb + blockIdx.x + 1;     // causal: self tiles 0..bx

    for (int t = 0; t < ntiles; t++) {
        bool kbphase = (t < nkb);
        int  kb0   = (t - nkb) * BNK;   // self key base
        int  jbase = t * BNK;           // kb top-idx base

        // (re)load Q tile: q2 for KB phase, roped q for self phase
        if (t == 0 || t == nkb) {
            const float* src = kbphase ? g_xq2 : g_xq;
            for (int i = tid; i < BMQ*HD/4; i += 256) {
                int row = i >> 5, c4 = i & 31;
                ((float4*)Qs)[i] =
                    ((const float4*)(src + (size_t)(q0+row)*HIDN + h*HD))[c4];
            }
        }
        // load K tile
        for (int i = tid; i < BNK*HD/4; i += 256) {
            int row = i >> 5, c4 = i & 31;
            float4 v;
            if (kbphase) {
                int j = jbase + row;
                if (j < NTOP) {
                    int kb = g_topidx[j];
                    v = ((const float4*)(kb_keys + (size_t)kb*KBSTRIDE + h*HD))[c4];
                } else v = make_float4(0.f,0.f,0.f,0.f);
            } else {
                v = ((const float4*)(g_xk + (size_t)(kb0+row)*HIDN + h*HD))[c4];
            }
            ((float4*)KVs)[i] = v;
        }
        __syncthreads();

        // scores: each thread computes 4x4 dots of length 128
        float sacc[4][4];
        #pragma unroll
        for (int a = 0; a < 4; a++)
            #pragma unroll
            for (int b = 0; b < 4; b++) sacc[a][b] = 0.f;
        #pragma unroll 8
        for (int d4 = 0; d4 < 32; d4++) {
            float4 qa[4], kb4[4];
            #pragma unroll
            for (int a = 0; a < 4; a++) qa[a]  = ((const float4*)Qs )[(ty*4+a)*32 + d4];
            #pragma unroll
            for (int b = 0; b < 4; b++) kb4[b] = ((const float4*)KVs)[(tx*4+b)*32 + d4];
            #pragma unroll
            for (int a = 0; a < 4; a++)
                #pragma unroll
                for (int b = 0; b < 4; b++)
                    sacc[a][b] += qa[a].x*kb4[b].x + qa[a].y*kb4[b].y
                                + qa[a].z*kb4[b].z + qa[a].w*kb4[b].w;
        }
        #pragma unroll
        for (int a = 0; a < 4; a++)
            #pragma unroll
            for (int b = 0; b < 4; b++) {
                int q = ty*4+a, kk = tx*4+b;
                float s;
                if (kbphase) {
                    s = (jbase + kk < NTOP) ? sacc[a][b]*ATT_SCALE + shift : -INFINITY;
                } else {
                    s = (kb0 + kk <= q0 + q) ? sacc[a][b]*ATT_SCALE : -INFINITY;
                }
                Ss[q*(BNK+1) + kk] = s;
            }
        __syncthreads();

        // online softmax row pass (one thread per query)
        if (tid < BMQ) {
            int q = tid;
            float mo = mrow[q];
            float mx = mo;
            #pragma unroll 8
            for (int kk = 0; kk < BNK; kk++) mx = fmaxf(mx, Ss[q*(BNK+1)+kk]);
            float corr = (mo == -INFINITY) ? 0.f : expf(mo - mx);
            float rs = 0.f;
            #pragma unroll 8
            for (int kk = 0; kk < BNK; kk++) {
                float p = expf(Ss[q*(BNK+1)+kk] - mx);
                Ss[q*(BNK+1)+kk] = p;
                rs += p;
            }
            lrow[q] = lrow[q]*corr + rs;
            crow[q] = corr;
            mrow[q] = mx;
        }
        __syncthreads();

        // rescale accumulators, overwrite KVs with V tile
        float cf = crow[qo];
        #pragma unroll
        for (int i = 0; i < 32; i++) acc[i] *= cf;
        for (int i = tid; i < BNK*HD/4; i += 256) {
            int row = i >> 5, c4 = i & 31;
            float4 v;
            if (kbphase) {
                int j = jbase + row;
                if (j < NTOP) {
                    int kb = g_topidx[j];
                    v = ((const float4*)(kb_values + (size_t)kb*KBSTRIDE + h*HD))[c4];
                } else v = make_float4(0.f,0.f,0.f,0.f);
            } else {
                v = ((const float4*)(g_xv + (size_t)(kb0+row)*HIDN + h*HD))[c4];
            }
            ((float4*)KVs)[i] = v;
        }
        __syncthreads();

        // PV: acc[q, dc..dc+31] += p * V
        #pragma unroll 4
        for (int kk = 0; kk < BNK; kk++) {
            float p = Ss[qo*(BNK+1) + kk];
            const float4* vr = (const float4*)&KVs[kk*HD + dc];
            #pragma unroll
            for (int i = 0; i < 8; i++) {
                float4 v = vr[i];
                acc[i*4+0] += p*v.x; acc[i*4+1] += p*v.y;
                acc[i*4+2] += p*v.z; acc[i*4+3] += p*v.w;
            }
        }
        __syncthreads();
    }

    float il = 1.f / lrow[qo];
    float* op = g_attn + (size_t)(q0+qo)*HIDN + h*HD + dc;
    #pragma unroll
    for (int i = 0; i < 8; i++)
        ((float4*)op)[i] = make_float4(acc[i*4]*il, acc[i*4+1]*il,
                                       acc[i*4+2]*il, acc[i*4+3]*il);
}

// ---------------- launch ---------------------------------------------------
extern "C" void kernel_launch(void* const* d_in, const int* in_sizes, int n_in,
                              void* d_out, int out_size)
{
    const float* hs   = (const float*)d_in[0];
    // d_in[1] = attention_mask (pure causal; reproduced analytically)
    const int*   pos  = (const int*)  d_in[2];
    const float* kbk  = (const float*)d_in[3];
    const float* kbv  = (const float*)d_in[4];
    const float* Wq   = (const float*)d_in[5];
    const float* Wq2  = (const float*)d_in[6];
    const float* Wk   = (const float*)d_in[7];
    const float* Wv   = (const float*)d_in[8];
    const float* Wo   = (const float*)d_in[9];
    const float* shft = (const float*)d_in[10];
    float* out = (float*)d_out;

    float *xq, *xq2, *xk, *xv, *attn;
    cudaGetSymbolAddress((void**)&xq,   g_xq);
    cudaGetSymbolAddress((void**)&xq2,  g_xq2);
    cudaGetSymbolAddress((void**)&xk,   g_xk);
    cudaGetSymbolAddress((void**)&xv,   g_xv);
    cudaGetSymbolAddress((void**)&attn, g_attn);

    cudaFuncSetAttribute(attn_kernel,
        cudaFuncAttributeMaxDynamicSharedMemorySize, ATTN_SMEM);

    dim3 gg(HIDN/128, SQ/128);
    gemm_nt<<<gg, 256>>>(hs, Wq,  xq,  SQ, HIDN, HIDN);
    gemm_nt<<<gg, 256>>>(hs, Wq2, xq2, SQ, HIDN, HIDN);
    gemm_nt<<<gg, 256>>>(hs, Wk,  xk,  SQ, HIDN, HIDN);
    gemm_nt<<<gg, 256>>>(hs, Wv,  xv,  SQ, HIDN, HIDN);

    rope_kernel<<<(SQ*HIDN)/256, 256>>>(pos);
    colsum_kernel<<<HIDN/256, 256>>>();
    kbscore_kernel<<<KBN/8, 256>>>(kbk);
    topk_kernel<<<1, 256>>>();

    attn_kernel<<<dim3(SQ/BMQ, NH), 256, ATTN_SMEM>>>(kbk, kbv, shft);

    gemm_nt<<<gg, 256>>>(attn, Wo, out, SQ, HIDN, HIDN);
}

// round 5
// speedup vs baseline: 1.7209x; 1.7209x over previous
#include <cuda_runtime.h>
#include <math.h>
#include <stdint.h>

#define SQ   1024
#define HIDN 4096
#define NH   32
#define HD   128
#define KBN  2048
#define KBSTRIDE 8192   // NUM_SLOTS * HID
#define NTOP 100
#define ATT_SCALE 0.08838834764831845f  // 1/sqrt(128)

#define BMQ 64
#define BNK 64
#define ATTN_SMEM ((BMQ*HD + BNK*HD + BMQ*(BNK+1) + 3*BMQ) * 4)

// ---------------- device scratch (static, allocation-free) ----------------
__device__ float g_xq  [SQ*HIDN];
__device__ float g_xq2 [SQ*HIDN];
__device__ float g_xk  [SQ*HIDN];
__device__ float g_xv  [SQ*HIDN];
__device__ float g_attn[SQ*HIDN];
__device__ float g_hsum [HIDN];
__device__ float g_q2sum[HIDN];
__device__ float g_kbscore[KBN];
__device__ int   g_topidx[NTOP];

// ======================= tf32 mma.sync GEMM ================================
// C[m,n] = sum_k A[m,k]*B[n,k];  A:MxK row-major, B:NxK row-major
// BM=BN=128, BK=16, 256 threads (8 warps as 2m x 4n, warp tile 64x32)
#define TBM 128
#define TBN 128
#define TBK 16
#define TSTR 20          // smem floats per row (16 data + 4 pad, 16B aligned)

__device__ __forceinline__ uint32_t smem_u32(const void* p) {
    uint32_t a;
    asm("{ .reg .u64 t; cvta.to.shared.u64 t, %1; cvt.u32.u64 %0, t; }"
        : "=r"(a) : "l"(p));
    return a;
}
__device__ __forceinline__ void cp16(uint32_t s, const void* g) {
    asm volatile("cp.async.cg.shared.global [%0], [%1], 16;" :: "r"(s), "l"(g) : "memory");
}
__device__ __forceinline__ uint32_t f2tf32(float f) {
    uint32_t u;
    asm("cvt.rna.tf32.f32 %0, %1;" : "=r"(u) : "f"(f));
    return u;
}
__device__ __forceinline__ void mma_tf32(float* c, const uint32_t* a, const uint32_t* b) {
    asm volatile(
        "mma.sync.aligned.m16n8k8.row.col.f32.tf32.tf32.f32 "
        "{%0,%1,%2,%3}, {%4,%5,%6,%7}, {%8,%9}, {%0,%1,%2,%3};"
        : "+f"(c[0]), "+f"(c[1]), "+f"(c[2]), "+f"(c[3])
        : "r"(a[0]), "r"(a[1]), "r"(a[2]), "r"(a[3]), "r"(b[0]), "r"(b[1]));
}

__global__ __launch_bounds__(256) void gemm_tf32(
    const float* __restrict__ A, const float* __restrict__ B,
    float* __restrict__ C, int M, int N, int K)
{
    __shared__ float As[2][TBM * TSTR];
    __shared__ float Bs[2][TBN * TSTR];

    int tid  = threadIdx.x;
    int wid  = tid >> 5;
    int lane = tid & 31;
    int bm = blockIdx.y * TBM, bn = blockIdx.x * TBN;

    int wm = (wid & 1) * 64;          // warp m offset
    int wn = (wid >> 1) * 32;         // warp n offset
    int g   = lane >> 2;              // groupID (row within m16 / col within n8)
    int tig = lane & 3;               // thread in group (col within k8)

    // per-thread load tasks: tile = 128 rows x 4 granules(16B) = 512 granules;
    // 256 threads -> 2 granules each (rows 0..63 and 64..127)
    int lr0 = tid >> 2,       lc0 = (tid & 3) * 4;
    int lr1 = lr0 + 64,       lc1 = lc0;
    uint32_t sA = smem_u32(&As[0][0]);
    uint32_t sB = smem_u32(&Bs[0][0]);

    float acc[4][4][4];   // [mt][nt][reg]
    #pragma unroll
    for (int i = 0; i < 4; i++)
        #pragma unroll
        for (int j = 0; j < 4; j++)
            #pragma unroll
            for (int r = 0; r < 4; r++) acc[i][j][r] = 0.f;

    const int NIT = K / TBK;

    // prologue: stage 0 <- chunk 0
    {
        cp16(sA + (lr0 * TSTR + lc0) * 4, A + (size_t)(bm + lr0) * K + lc0);
        cp16(sA + (lr1 * TSTR + lc1) * 4, A + (size_t)(bm + lr1) * K + lc1);
        cp16(sB + (lr0 * TSTR + lc0) * 4, B + (size_t)(bn + lr0) * K + lc0);
        cp16(sB + (lr1 * TSTR + lc1) * 4, B + (size_t)(bn + lr1) * K + lc1);
        asm volatile("cp.async.commit_group;" ::: "memory");
    }

    for (int it = 0; it < NIT; it++) {
        int cur = it & 1;
        if (it + 1 < NIT) {
            int k0 = (it + 1) * TBK;
            uint32_t dA = sA + (cur ^ 1) * TBM * TSTR * 4;
            uint32_t dB = sB + (cur ^ 1) * TBN * TSTR * 4;
            cp16(dA + (lr0 * TSTR + lc0) * 4, A + (size_t)(bm + lr0) * K + k0 + lc0);
            cp16(dA + (lr1 * TSTR + lc1) * 4, A + (size_t)(bm + lr1) * K + k0 + lc1);
            cp16(dB + (lr0 * TSTR + lc0) * 4, B + (size_t)(bn + lr0) * K + k0 + lc0);
            cp16(dB + (lr1 * TSTR + lc1) * 4, B + (size_t)(bn + lr1) * K + k0 + lc1);
            asm volatile("cp.async.commit_group;" ::: "memory");
            asm volatile("cp.async.wait_group 1;" ::: "memory");
        } else {
            asm volatile("cp.async.wait_group 0;" ::: "memory");
        }
        __syncthreads();

        const float* a_s = As[cur];
        const float* b_s = Bs[cur];
        #pragma unroll
        for (int ks = 0; ks < 2; ks++) {
            int kb = ks * 8;
            uint32_t af[4][4];
            #pragma unroll
            for (int mt = 0; mt < 4; mt++) {
                int r = wm + mt * 16 + g;
                af[mt][0] = f2tf32(a_s[ r      * TSTR + kb + tig]);
                af[mt][1] = f2tf32(a_s[(r + 8) * TSTR + kb + tig]);
                af[mt][2] = f2tf32(a_s[ r      * TSTR + kb + tig + 4]);
                af[mt][3] = f2tf32(a_s[(r + 8) * TSTR + kb + tig + 4]);
            }
            uint32_t bf[4][2];
            #pragma unroll
            for (int nt = 0; nt < 4; nt++) {
                int n = wn + nt * 8 + g;
                bf[nt][0] = f2tf32(b_s[n * TSTR + kb + tig]);
                bf[nt][1] = f2tf32(b_s[n * TSTR + kb + tig + 4]);
            }
            #pragma unroll
            for (int mt = 0; mt < 4; mt++)
                #pragma unroll
                for (int nt = 0; nt < 4; nt++)
                    mma_tf32(acc[mt][nt], af[mt], bf[nt]);
        }
        __syncthreads();
    }

    // epilogue
    #pragma unroll
    for (int mt = 0; mt < 4; mt++) {
        #pragma unroll
        for (int nt = 0; nt < 4; nt++) {
            int row = bm + wm + mt * 16 + g;
            int col = bn + wn + nt * 8 + 2 * tig;
            float* c0 = C + (size_t)row * N + col;
            float* c1 = C + (size_t)(row + 8) * N + col;
            ((float2*)c0)[0] = make_float2(acc[mt][nt][0], acc[mt][nt][1]);
            ((float2*)c1)[0] = make_float2(acc[mt][nt][2], acc[mt][nt][3]);
        }
    }
}

// ---------------- RoPE in place on g_xq and g_xk --------------------------
__global__ void rope_kernel(const int* __restrict__ pos_ids)
{
    const int total = SQ * HIDN / 2;   // pairs per tensor
    int i = blockIdx.x * blockDim.x + threadIdx.x;
    float* X = g_xq;
    if (i >= total) { X = g_xk; i -= total; }
    if (i >= total) return;
    int s = i / (HIDN/2);
    int r = i - s * (HIDN/2);
    int h = r >> 6, d = r & 63;
    int c = s*HIDN + h*HD + d;
    float pos = (float)pos_ids[s];
    float inv = expf((float)d * (-9.210340371976184f / 64.0f));
    float f = pos * inv;
    float cs, sn;
    sincosf(f, &sn, &cs);
    float x1 = X[c], x2 = X[c + 64];
    X[c]      = x1*cs - x2*sn;
    X[c + 64] = x2*cs + x1*sn;
}

// ---------------- fp32 top-k scoring path (independent of tf32 GEMMs) -----
__global__ void hsum_kernel(const float* __restrict__ hs)
{
    int c = blockIdx.x * 256 + threadIdx.x;
    float s = 0.f;
    for (int r = 0; r < SQ; r++) s += hs[(size_t)r*HIDN + c];
    g_hsum[c] = s;
}

__global__ void q2sum_kernel(const float* __restrict__ Wq2)
{
    int n    = blockIdx.x * 8 + (threadIdx.x >> 5);
    int lane = threadIdx.x & 31;
    const float* row = Wq2 + (size_t)n * HIDN;
    float s = 0.f;
    for (int i = lane; i < HIDN; i += 32) s += row[i] * g_hsum[i];
    #pragma unroll
    for (int o = 16; o; o >>= 1) s += __shfl_xor_sync(0xffffffffu, s, o);
    if (lane == 0) g_q2sum[n] = s;
}

__global__ void kbscore_kernel(const float* __restrict__ kb_keys)
{
    int kb   = blockIdx.x * 8 + (threadIdx.x >> 5);
    int lane = threadIdx.x & 31;
    const float* row = kb_keys + (size_t)kb * KBSTRIDE;
    float s = 0.f;
    for (int i = lane; i < HIDN; i += 32) s += row[i] * g_q2sum[i];
    #pragma unroll
    for (int o = 16; o; o >>= 1) s += __shfl_xor_sync(0xffffffffu, s, o);
    if (lane == 0) g_kbscore[kb] = s;
}

// ---------------- top-100 by iterative argmax (single block) --------------
__global__ void topk_kernel()
{
    __shared__ float sv[KBN];
    __shared__ float rv[256];
    __shared__ int   ri[256];
    int t = threadIdx.x;
    for (int i = t; i < KBN; i += 256) sv[i] = g_kbscore[i];
    __syncthreads();
    for (int it = 0; it < NTOP; it++) {
        float best = -INFINITY; int bi = 0;
        for (int i = t; i < KBN; i += 256) {
            float v = sv[i];
            if (v > best) { best = v; bi = i; }
        }
        rv[t] = best; ri[t] = bi;
        __syncthreads();
        for (int o = 128; o; o >>= 1) {
            if (t < o && rv[t+o] > rv[t]) { rv[t] = rv[t+o]; ri[t] = ri[t+o]; }
            __syncthreads();
        }
        if (t == 0) { g_topidx[it] = ri[0]; sv[ri[0]] = -INFINITY; }
        __syncthreads();
    }
}

// ---------------- flash attention over [KB-topk ; causal self] ------------
__global__ __launch_bounds__(256) void attn_kernel(
    const float* __restrict__ kb_keys, const float* __restrict__ kb_values,
    const float* __restrict__ score_shift)
{
    extern __shared__ float sm[];
    float* Qs   = sm;                         // BMQ * 128
    float* KVs  = Qs  + BMQ*HD;               // BNK * 128
    float* Ss   = KVs + BNK*HD;               // BMQ * (BNK+1)
    float* mrow = Ss  + BMQ*(BNK+1);
    float* lrow = mrow + BMQ;
    float* crow = lrow + BMQ;

    int h  = blockIdx.y;
    int q0 = blockIdx.x * BMQ;
    int tid = threadIdx.x;
    int tx = tid & 15, ty = tid >> 4;   // score tile mapping (16x16)
    int qo = tid >> 2;                  // owned query row (0..63)
    int dc = (tid & 3) * 32;            // owned dim chunk base

    float acc[32];
    #pragma unroll
    for (int i = 0; i < 32; i++) acc[i] = 0.f;
    if (tid < BMQ) { mrow[tid] = -INFINITY; lrow[tid] = 0.f; }

    float shift = score_shift[h];

    const int nkb    = (NTOP + BNK - 1) / BNK;   // 2
    const int ntiles = nkb + blockIdx.x + 1;     // causal: self tiles 0..bx

    for (int t = 0; t < ntiles; t++) {
        bool kbphase = (t < nkb);
        int  kb0   = (t - nkb) * BNK;   // self key base
        int  jbase = t * BNK;           // kb top-idx base

        if (t == 0 || t == nkb) {
            const float* src = kbphase ? g_xq2 : g_xq;
            for (int i = tid; i < BMQ*HD/4; i += 256) {
                int row = i >> 5, c4 = i & 31;
                ((float4*)Qs)[i] =
                    ((const float4*)(src + (size_t)(q0+row)*HIDN + h*HD))[c4];
            }
        }
        for (int i = tid; i < BNK*HD/4; i += 256) {
            int row = i >> 5, c4 = i & 31;
            float4 v;
            if (kbphase) {
                int j = jbase + row;
                if (j < NTOP) {
                    int kb = g_topidx[j];
                    v = ((const float4*)(kb_keys + (size_t)kb*KBSTRIDE + h*HD))[c4];
                } else v = make_float4(0.f,0.f,0.f,0.f);
            } else {
                v = ((const float4*)(g_xk + (size_t)(kb0+row)*HIDN + h*HD))[c4];
            }
            ((float4*)KVs)[i] = v;
        }
        __syncthreads();

        float sacc[4][4];
        #pragma unroll
        for (int a = 0; a < 4; a++)
            #pragma unroll
            for (int b = 0; b < 4; b++) sacc[a][b] = 0.f;
        #pragma unroll 8
        for (int d4 = 0; d4 < 32; d4++) {
            float4 qa[4], kb4[4];
            #pragma unroll
            for (int a = 0; a < 4; a++) qa[a]  = ((const float4*)Qs )[(ty*4+a)*32 + d4];
            #pragma unroll
            for (int b = 0; b < 4; b++) kb4[b] = ((const float4*)KVs)[(tx*4+b)*32 + d4];
            #pragma unroll
            for (int a = 0; a < 4; a++)
                #pragma unroll
                for (int b = 0; b < 4; b++)
                    sacc[a][b] += qa[a].x*kb4[b].x + qa[a].y*kb4[b].y
                                + qa[a].z*kb4[b].z + qa[a].w*kb4[b].w;
        }
        #pragma unroll
        for (int a = 0; a < 4; a++)
            #pragma unroll
            for (int b = 0; b < 4; b++) {
                int q = ty*4+a, kk = tx*4+b;
                float s;
                if (kbphase) {
                    s = (jbase + kk < NTOP) ? sacc[a][b]*ATT_SCALE + shift : -INFINITY;
                } else {
                    s = (kb0 + kk <= q0 + q) ? sacc[a][b]*ATT_SCALE : -INFINITY;
                }
                Ss[q*(BNK+1) + kk] = s;
            }
        __syncthreads();

        if (tid < BMQ) {
            int q = tid;
            float mo = mrow[q];
            float mx = mo;
            #pragma unroll 8
            for (int kk = 0; kk < BNK; kk++) mx = fmaxf(mx, Ss[q*(BNK+1)+kk]);
            float corr = (mo == -INFINITY) ? 0.f : expf(mo - mx);
            float rs = 0.f;
            #pragma unroll 8
            for (int kk = 0; kk < BNK; kk++) {
                float p = expf(Ss[q*(BNK+1)+kk] - mx);
                Ss[q*(BNK+1)+kk] = p;
                rs += p;
            }
            lrow[q] = lrow[q]*corr + rs;
            crow[q] = corr;
            mrow[q] = mx;
        }
        __syncthreads();

        float cf = crow[qo];
        #pragma unroll
        for (int i = 0; i < 32; i++) acc[i] *= cf;
        for (int i = tid; i < BNK*HD/4; i += 256) {
            int row = i >> 5, c4 = i & 31;
            float4 v;
            if (kbphase) {
                int j = jbase + row;
                if (j < NTOP) {
                    int kb = g_topidx[j];
                    v = ((const float4*)(kb_values + (size_t)kb*KBSTRIDE + h*HD))[c4];
                } else v = make_float4(0.f,0.f,0.f,0.f);
            } else {
                v = ((const float4*)(g_xv + (size_t)(kb0+row)*HIDN + h*HD))[c4];
            }
            ((float4*)KVs)[i] = v;
        }
        __syncthreads();

        #pragma unroll 4
        for (int kk = 0; kk < BNK; kk++) {
            float p = Ss[qo*(BNK+1) + kk];
            const float4* vr = (const float4*)&KVs[kk*HD + dc];
            #pragma unroll
            for (int i = 0; i < 8; i++) {
                float4 v = vr[i];
                acc[i*4+0] += p*v.x; acc[i*4+1] += p*v.y;
                acc[i*4+2] += p*v.z; acc[i*4+3] += p*v.w;
            }
        }
        __syncthreads();
    }

    float il = 1.f / lrow[qo];
    float* op = g_attn + (size_t)(q0+qo)*HIDN + h*HD + dc;
    #pragma unroll
    for (int i = 0; i < 8; i++)
        ((float4*)op)[i] = make_float4(acc[i*4]*il, acc[i*4+1]*il,
                                       acc[i*4+2]*il, acc[i*4+3]*il);
}

// ---------------- launch ---------------------------------------------------
extern "C" void kernel_launch(void* const* d_in, const int* in_sizes, int n_in,
                              void* d_out, int out_size)
{
    const float* hs   = (const float*)d_in[0];
    // d_in[1] = attention_mask (pure causal; reproduced analytically)
    const int*   pos  = (const int*)  d_in[2];
    const float* kbk  = (const float*)d_in[3];
    const float* kbv  = (const float*)d_in[4];
    const float* Wq   = (const float*)d_in[5];
    const float* Wq2  = (const float*)d_in[6];
    const float* Wk   = (const float*)d_in[7];
    const float* Wv   = (const float*)d_in[8];
    const float* Wo   = (const float*)d_in[9];
    const float* shft = (const float*)d_in[10];
    float* out = (float*)d_out;

    float *xq, *xq2, *xk, *xv, *attn;
    cudaGetSymbolAddress((void**)&xq,   g_xq);
    cudaGetSymbolAddress((void**)&xq2,  g_xq2);
    cudaGetSymbolAddress((void**)&xk,   g_xk);
    cudaGetSymbolAddress((void**)&xv,   g_xv);
    cudaGetSymbolAddress((void**)&attn, g_attn);

    cudaFuncSetAttribute(attn_kernel,
        cudaFuncAttributeMaxDynamicSharedMemorySize, ATTN_SMEM);

    dim3 gg(HIDN/TBN, SQ/TBM);   // (32, 8)
    gemm_tf32<<<gg, 256>>>(hs, Wq,  xq,  SQ, HIDN, HIDN);
    gemm_tf32<<<gg, 256>>>(hs, Wq2, xq2, SQ, HIDN, HIDN);
    gemm_tf32<<<gg, 256>>>(hs, Wk,  xk,  SQ, HIDN, HIDN);
    gemm_tf32<<<gg, 256>>>(hs, Wv,  xv,  SQ, HIDN, HIDN);

    rope_kernel<<<(SQ*HIDN)/256, 256>>>(pos);

    // fp32 top-k path (independent of tf32 precision)
    hsum_kernel<<<HIDN/256, 256>>>(hs);
    q2sum_kernel<<<HIDN/8, 256>>>(Wq2);
    kbscore_kernel<<<KBN/8, 256>>>(kbk);
    topk_kernel<<<1, 256>>>();

    attn_kernel<<<dim3(SQ/BMQ, NH), 256, ATTN_SMEM>>>(kbk, kbv, shft);

    gemm_tf32<<<gg, 256>>>(attn, Wo, out, SQ, HIDN, HIDN);
}

// round 6
// speedup vs baseline: 2.2439x; 1.3039x over previous
#include <cuda_runtime.h>
#include <math.h>
#include <stdint.h>

#define SQ   1024
#define HIDN 4096
#define NH   32
#define HD   128
#define KBN  2048
#define KBSTRIDE 8192   // NUM_SLOTS * HID
#define NTOP 100
#define ATT_SCALE 0.08838834764831845f  // 1/sqrt(128)

#define BMQ 64
#define BNK 64
#define ATTN_SMEM ((BMQ*HD + BNK*HD + BMQ*(BNK+1) + 3*BMQ) * 4)

// swizzled float4 index into a [rows][32 float4] tile: kills the 16-way
// bank conflict on K loads (rows accessed at stride 4 -> key = (row>>2)&7)
#define SW(row, c4) (((row) << 5) + ((c4) ^ (((row) >> 2) & 7)))

// ---------------- device scratch (static, allocation-free) ----------------
__device__ float g_xq  [SQ*HIDN];
__device__ float g_xq2 [SQ*HIDN];
__device__ float g_xk  [SQ*HIDN];
__device__ float g_xv  [SQ*HIDN];
__device__ float g_attn[SQ*HIDN];
__device__ float g_hsum [HIDN];
__device__ float g_q2sum[HIDN];
__device__ float g_kbscore[KBN];
__device__ int   g_topidx[NTOP];

// ======================= tf32 mma.sync GEMM ================================
// C[m,n] = sum_k A[m,k]*B[n,k];  A:MxK row-major, B:NxK row-major
// BM=BN=128, BK=16, 256 threads (8 warps as 2m x 4n, warp tile 64x32)
#define TBM 128
#define TBN 128
#define TBK 16
#define TSTR 20          // smem floats per row (16 data + 4 pad, 16B aligned)

__device__ __forceinline__ uint32_t smem_u32(const void* p) {
    uint32_t a;
    asm("{ .reg .u64 t; cvta.to.shared.u64 t, %1; cvt.u32.u64 %0, t; }"
        : "=r"(a) : "l"(p));
    return a;
}
__device__ __forceinline__ void cp16(uint32_t s, const void* g) {
    asm volatile("cp.async.cg.shared.global [%0], [%1], 16;" :: "r"(s), "l"(g) : "memory");
}
__device__ __forceinline__ uint32_t f2tf32(float f) {
    uint32_t u;
    asm("cvt.rna.tf32.f32 %0, %1;" : "=r"(u) : "f"(f));
    return u;
}
__device__ __forceinline__ void mma_tf32(float* c, const uint32_t* a, const uint32_t* b) {
    asm volatile(
        "mma.sync.aligned.m16n8k8.row.col.f32.tf32.tf32.f32 "
        "{%0,%1,%2,%3}, {%4,%5,%6,%7}, {%8,%9}, {%0,%1,%2,%3};"
        : "+f"(c[0]), "+f"(c[1]), "+f"(c[2]), "+f"(c[3])
        : "r"(a[0]), "r"(a[1]), "r"(a[2]), "r"(a[3]), "r"(b[0]), "r"(b[1]));
}

__global__ __launch_bounds__(256, 2) void gemm_tf32(
    const float* __restrict__ A, const float* __restrict__ B,
    float* __restrict__ C, int M, int N, int K)
{
    __shared__ float As[2][TBM * TSTR];
    __shared__ float Bs[2][TBN * TSTR];

    int tid  = threadIdx.x;
    int wid  = tid >> 5;
    int lane = tid & 31;
    int bm = blockIdx.y * TBM, bn = blockIdx.x * TBN;

    int wm = (wid & 1) * 64;          // warp m offset
    int wn = (wid >> 1) * 32;         // warp n offset
    int g   = lane >> 2;              // groupID (row within m16 / col within n8)
    int tig = lane & 3;               // thread in group (col within k8)

    // per-thread load tasks: tile = 128 rows x 4 granules(16B) = 512 granules;
    // 256 threads -> 2 granules each (rows 0..63 and 64..127)
    int lr0 = tid >> 2,       lc0 = (tid & 3) * 4;
    int lr1 = lr0 + 64,       lc1 = lc0;
    uint32_t sA = smem_u32(&As[0][0]);
    uint32_t sB = smem_u32(&Bs[0][0]);

    float acc[4][4][4];   // [mt][nt][reg]
    #pragma unroll
    for (int i = 0; i < 4; i++)
        #pragma unroll
        for (int j = 0; j < 4; j++)
            #pragma unroll
            for (int r = 0; r < 4; r++) acc[i][j][r] = 0.f;

    const int NIT = K / TBK;

    // prologue: stage 0 <- chunk 0
    {
        cp16(sA + (lr0 * TSTR + lc0) * 4, A + (size_t)(bm + lr0) * K + lc0);
        cp16(sA + (lr1 * TSTR + lc1) * 4, A + (size_t)(bm + lr1) * K + lc1);
        cp16(sB + (lr0 * TSTR + lc0) * 4, B + (size_t)(bn + lr0) * K + lc0);
        cp16(sB + (lr1 * TSTR + lc1) * 4, B + (size_t)(bn + lr1) * K + lc1);
        asm volatile("cp.async.commit_group;" ::: "memory");
    }

    for (int it = 0; it < NIT; it++) {
        int cur = it & 1;
        if (it + 1 < NIT) {
            int k0 = (it + 1) * TBK;
            uint32_t dA = sA + (cur ^ 1) * TBM * TSTR * 4;
            uint32_t dB = sB + (cur ^ 1) * TBN * TSTR * 4;
            cp16(dA + (lr0 * TSTR + lc0) * 4, A + (size_t)(bm + lr0) * K + k0 + lc0);
            cp16(dA + (lr1 * TSTR + lc1) * 4, A + (size_t)(bm + lr1) * K + k0 + lc1);
            cp16(dB + (lr0 * TSTR + lc0) * 4, B + (size_t)(bn + lr0) * K + k0 + lc0);
            cp16(dB + (lr1 * TSTR + lc1) * 4, B + (size_t)(bn + lr1) * K + k0 + lc1);
            asm volatile("cp.async.commit_group;" ::: "memory");
            asm volatile("cp.async.wait_group 1;" ::: "memory");
        } else {
            asm volatile("cp.async.wait_group 0;" ::: "memory");
        }
        __syncthreads();

        const float* a_s = As[cur];
        const float* b_s = Bs[cur];
        #pragma unroll
        for (int ks = 0; ks < 2; ks++) {
            int kb = ks * 8;
            uint32_t af[4][4];
            #pragma unroll
            for (int mt = 0; mt < 4; mt++) {
                int r = wm + mt * 16 + g;
                af[mt][0] = f2tf32(a_s[ r      * TSTR + kb + tig]);
                af[mt][1] = f2tf32(a_s[(r + 8) * TSTR + kb + tig]);
                af[mt][2] = f2tf32(a_s[ r      * TSTR + kb + tig + 4]);
                af[mt][3] = f2tf32(a_s[(r + 8) * TSTR + kb + tig + 4]);
            }
            uint32_t bf[4][2];
            #pragma unroll
            for (int nt = 0; nt < 4; nt++) {
                int n = wn + nt * 8 + g;
                bf[nt][0] = f2tf32(b_s[n * TSTR + kb + tig]);
                bf[nt][1] = f2tf32(b_s[n * TSTR + kb + tig + 4]);
            }
            #pragma unroll
            for (int mt = 0; mt < 4; mt++)
                #pragma unroll
                for (int nt = 0; nt < 4; nt++)
                    mma_tf32(acc[mt][nt], af[mt], bf[nt]);
        }
        __syncthreads();
    }

    // epilogue
    #pragma unroll
    for (int mt = 0; mt < 4; mt++) {
        #pragma unroll
        for (int nt = 0; nt < 4; nt++) {
            int row = bm + wm + mt * 16 + g;
            int col = bn + wn + nt * 8 + 2 * tig;
            float* c0 = C + (size_t)row * N + col;
            float* c1 = C + (size_t)(row + 8) * N + col;
            ((float2*)c0)[0] = make_float2(acc[mt][nt][0], acc[mt][nt][1]);
            ((float2*)c1)[0] = make_float2(acc[mt][nt][2], acc[mt][nt][3]);
        }
    }
}

// ---------------- RoPE in place on g_xq and g_xk --------------------------
__global__ void rope_kernel(const int* __restrict__ pos_ids)
{
    const int total = SQ * HIDN / 2;   // pairs per tensor
    int i = blockIdx.x * blockDim.x + threadIdx.x;
    float* X = g_xq;
    if (i >= total) { X = g_xk; i -= total; }
    if (i >= total) return;
    int s = i / (HIDN/2);
    int r = i - s * (HIDN/2);
    int h = r >> 6, d = r & 63;
    int c = s*HIDN + h*HD + d;
    float pos = (float)pos_ids[s];
    float inv = expf((float)d * (-9.210340371976184f / 64.0f));
    float f = pos * inv;
    float cs, sn;
    sincosf(f, &sn, &cs);
    float x1 = X[c], x2 = X[c + 64];
    X[c]      = x1*cs - x2*sn;
    X[c + 64] = x2*cs + x1*sn;
}

// ---------------- fp32 top-k scoring path (independent of tf32 GEMMs) -----
__global__ void hsum_kernel(const float* __restrict__ hs)
{
    int c = blockIdx.x * 256 + threadIdx.x;
    float s = 0.f;
    for (int r = 0; r < SQ; r++) s += hs[(size_t)r*HIDN + c];
    g_hsum[c] = s;
}

__global__ void q2sum_kernel(const float* __restrict__ Wq2)
{
    int n    = blockIdx.x * 8 + (threadIdx.x >> 5);
    int lane = threadIdx.x & 31;
    const float* row = Wq2 + (size_t)n * HIDN;
    float s = 0.f;
    for (int i = lane; i < HIDN; i += 32) s += row[i] * g_hsum[i];
    #pragma unroll
    for (int o = 16; o; o >>= 1) s += __shfl_xor_sync(0xffffffffu, s, o);
    if (lane == 0) g_q2sum[n] = s;
}

__global__ void kbscore_kernel(const float* __restrict__ kb_keys)
{
    int kb   = blockIdx.x * 8 + (threadIdx.x >> 5);
    int lane = threadIdx.x & 31;
    const float* row = kb_keys + (size_t)kb * KBSTRIDE;
    float s = 0.f;
    for (int i = lane; i < HIDN; i += 32) s += row[i] * g_q2sum[i];
    #pragma unroll
    for (int o = 16; o; o >>= 1) s += __shfl_xor_sync(0xffffffffu, s, o);
    if (lane == 0) g_kbscore[kb] = s;
}

// ---------------- top-100 by iterative argmax (single block) --------------
__global__ void topk_kernel()
{
    __shared__ float sv[KBN];
    __shared__ float rv[256];
    __shared__ int   ri[256];
    int t = threadIdx.x;
    for (int i = t; i < KBN; i += 256) sv[i] = g_kbscore[i];
    __syncthreads();
    for (int it = 0; it < NTOP; it++) {
        float best = -INFINITY; int bi = 0;
        for (int i = t; i < KBN; i += 256) {
            float v = sv[i];
            if (v > best) { best = v; bi = i; }
        }
        rv[t] = best; ri[t] = bi;
        __syncthreads();
        for (int o = 128; o; o >>= 1) {
            if (t < o && rv[t+o] > rv[t]) { rv[t] = rv[t+o]; ri[t] = ri[t+o]; }
            __syncthreads();
        }
        if (t == 0) { g_topidx[it] = ri[0]; sv[ri[0]] = -INFINITY; }
        __syncthreads();
    }
}

// ---------------- flash attention over [KB-topk ; causal self] ------------
__global__ __launch_bounds__(256) void attn_kernel(
    const float* __restrict__ kb_keys, const float* __restrict__ kb_values,
    const float* __restrict__ score_shift)
{
    extern __shared__ float sm[];
    float* Qs   = sm;                         // BMQ * 128 (swizzled float4)
    float* KVs  = Qs  + BMQ*HD;               // BNK * 128 (swizzled float4)
    float* Ss   = KVs + BNK*HD;               // BMQ * (BNK+1)
    float* mrow = Ss  + BMQ*(BNK+1);
    float* lrow = mrow + BMQ;
    float* crow = lrow + BMQ;

    int h  = blockIdx.y;
    int q0 = blockIdx.x * BMQ;
    int tid = threadIdx.x;
    int tx = tid & 15, ty = tid >> 4;   // score tile mapping (16x16)
    int qo = tid >> 2;                  // owned query row (0..63)
    int dc4 = (tid & 3) * 8;            // owned dim chunk base (float4 units)

    float acc[32];
    #pragma unroll
    for (int i = 0; i < 32; i++) acc[i] = 0.f;
    if (tid < BMQ) { mrow[tid] = -INFINITY; lrow[tid] = 0.f; }

    float shift = score_shift[h];

    const int nkb    = (NTOP + BNK - 1) / BNK;   // 2
    const int ntiles = nkb + blockIdx.x + 1;     // causal: self tiles 0..bx

    float4* Q4  = (float4*)Qs;
    float4* KV4 = (float4*)KVs;

    for (int t = 0; t < ntiles; t++) {
        bool kbphase = (t < nkb);
        int  kb0   = (t - nkb) * BNK;   // self key base
        int  jbase = t * BNK;           // kb top-idx base

        if (t == 0 || t == nkb) {
            const float* src = kbphase ? g_xq2 : g_xq;
            for (int i = tid; i < BMQ*HD/4; i += 256) {
                int row = i >> 5, c4 = i & 31;
                Q4[SW(row, c4)] =
                    ((const float4*)(src + (size_t)(q0+row)*HIDN + h*HD))[c4];
            }
        }
        for (int i = tid; i < BNK*HD/4; i += 256) {
            int row = i >> 5, c4 = i & 31;
            float4 v;
            if (kbphase) {
                int j = jbase + row;
                if (j < NTOP) {
                    int kb = g_topidx[j];
                    v = ((const float4*)(kb_keys + (size_t)kb*KBSTRIDE + h*HD))[c4];
                } else v = make_float4(0.f,0.f,0.f,0.f);
            } else {
                v = ((const float4*)(g_xk + (size_t)(kb0+row)*HIDN + h*HD))[c4];
            }
            KV4[SW(row, c4)] = v;
        }
        __syncthreads();

        float sacc[4][4];
        #pragma unroll
        for (int a = 0; a < 4; a++)
            #pragma unroll
            for (int b = 0; b < 4; b++) sacc[a][b] = 0.f;
        #pragma unroll 8
        for (int d4 = 0; d4 < 32; d4++) {
            float4 qa[4], kb4[4];
            #pragma unroll
            for (int a = 0; a < 4; a++) qa[a]  = Q4 [SW(ty*4+a, d4)];
            #pragma unroll
            for (int b = 0; b < 4; b++) kb4[b] = KV4[SW(tx*4+b, d4)];
            #pragma unroll
            for (int a = 0; a < 4; a++)
                #pragma unroll
                for (int b = 0; b < 4; b++)
                    sacc[a][b] += qa[a].x*kb4[b].x + qa[a].y*kb4[b].y
                                + qa[a].z*kb4[b].z + qa[a].w*kb4[b].w;
        }
        #pragma unroll
        for (int a = 0; a < 4; a++)
            #pragma unroll
            for (int b = 0; b < 4; b++) {
                int q = ty*4+a, kk = tx*4+b;
                float s;
                if (kbphase) {
                    s = (jbase + kk < NTOP) ? sacc[a][b]*ATT_SCALE + shift : -INFINITY;
                } else {
                    s = (kb0 + kk <= q0 + q) ? sacc[a][b]*ATT_SCALE : -INFINITY;
                }
                Ss[q*(BNK+1) + kk] = s;
            }
        __syncthreads();

        if (tid < BMQ) {
            int q = tid;
            float mo = mrow[q];
            float mx = mo;
            #pragma unroll 8
            for (int kk = 0; kk < BNK; kk++) mx = fmaxf(mx, Ss[q*(BNK+1)+kk]);
            float corr = (mo == -INFINITY) ? 0.f : expf(mo - mx);
            float rs = 0.f;
            #pragma unroll 8
            for (int kk = 0; kk < BNK; kk++) {
                float p = expf(Ss[q*(BNK+1)+kk] - mx);
                Ss[q*(BNK+1)+kk] = p;
                rs += p;
            }
            lrow[q] = lrow[q]*corr + rs;
            crow[q] = corr;
            mrow[q] = mx;
        }
        __syncthreads();

        float cf = crow[qo];
        #pragma unroll
        for (int i = 0; i < 32; i++) acc[i] *= cf;
        for (int i = tid; i < BNK*HD/4; i += 256) {
            int row = i >> 5, c4 = i & 31;
            float4 v;
            if (kbphase) {
                int j = jbase + row;
                if (j < NTOP) {
                    int kb = g_topidx[j];
                    v = ((const float4*)(kb_values + (size_t)kb*KBSTRIDE + h*HD))[c4];
                } else v = make_float4(0.f,0.f,0.f,0.f);
            } else {
                v = ((const float4*)(g_xv + (size_t)(kb0+row)*HIDN + h*HD))[c4];
            }
            KV4[SW(row, c4)] = v;
        }
        __syncthreads();

        #pragma unroll 4
        for (int kk = 0; kk < BNK; kk++) {
            float p = Ss[qo*(BNK+1) + kk];
            #pragma unroll
            for (int i = 0; i < 8; i++) {
                float4 v = KV4[SW(kk, dc4 + i)];
                acc[i*4+0] += p*v.x; acc[i*4+1] += p*v.y;
                acc[i*4+2] += p*v.z; acc[i*4+3] += p*v.w;
            }
        }
        __syncthreads();
    }

    float il = 1.f / lrow[qo];
    float* op = g_attn + (size_t)(q0+qo)*HIDN + h*HD + dc4*4;
    #pragma unroll
    for (int i = 0; i < 8; i++)
        ((float4*)op)[i] = make_float4(acc[i*4]*il, acc[i*4+1]*il,
                                       acc[i*4+2]*il, acc[i*4+3]*il);
}

// ---------------- launch ---------------------------------------------------
extern "C" void kernel_launch(void* const* d_in, const int* in_sizes, int n_in,
                              void* d_out, int out_size)
{
    const float* hs   = (const float*)d_in[0];
    // d_in[1] = attention_mask (pure causal; reproduced analytically)
    const int*   pos  = (const int*)  d_in[2];
    const float* kbk  = (const float*)d_in[3];
    const float* kbv  = (const float*)d_in[4];
    const float* Wq   = (const float*)d_in[5];
    const float* Wq2  = (const float*)d_in[6];
    const float* Wk   = (const float*)d_in[7];
    const float* Wv   = (const float*)d_in[8];
    const float* Wo   = (const float*)d_in[9];
    const float* shft = (const float*)d_in[10];
    float* out = (float*)d_out;

    float *xq, *xq2, *xk, *xv, *attn;
    cudaGetSymbolAddress((void**)&xq,   g_xq);
    cudaGetSymbolAddress((void**)&xq2,  g_xq2);
    cudaGetSymbolAddress((void**)&xk,   g_xk);
    cudaGetSymbolAddress((void**)&xv,   g_xv);
    cudaGetSymbolAddress((void**)&attn, g_attn);

    cudaFuncSetAttribute(attn_kernel,
        cudaFuncAttributeMaxDynamicSharedMemorySize, ATTN_SMEM);

    dim3 gg(HIDN/TBN, SQ/TBM);   // (32, 8)
    gemm_tf32<<<gg, 256>>>(hs, Wq,  xq,  SQ, HIDN, HIDN);
    gemm_tf32<<<gg, 256>>>(hs, Wq2, xq2, SQ, HIDN, HIDN);
    gemm_tf32<<<gg, 256>>>(hs, Wk,  xk,  SQ, HIDN, HIDN);
    gemm_tf32<<<gg, 256>>>(hs, Wv,  xv,  SQ, HIDN, HIDN);

    rope_kernel<<<(SQ*HIDN)/256, 256>>>(pos);

    // fp32 top-k path (independent of tf32 precision)
    hsum_kernel<<<HIDN/256, 256>>>(hs);
    q2sum_kernel<<<HIDN/8, 256>>>(Wq2);
    kbscore_kernel<<<KBN/8, 256>>>(kbk);
    topk_kernel<<<1, 256>>>();

    attn_kernel<<<dim3(SQ/BMQ, NH), 256, ATTN_SMEM>>>(kbk, kbv, shft);

    gemm_tf32<<<gg, 256>>>(attn, Wo, out, SQ, HIDN, HIDN);
}